// round 16
// baseline (speedup 1.0000x reference)
#include <cuda_runtime.h>

#define N_NODES 32768
#define N_EDGES 262144
#define H 128

// Scratch (device globals — no allocation allowed)
__device__ float g_x[N_NODES * 384];        // interaction MLP output
__device__ float g_qacc[N_NODES * H];       // scalar message accumulator
__device__ float g_muacc[N_NODES * 384];    // vector message accumulator
__device__ float g_deg[N_NODES];            // in-degree

__device__ __forceinline__ float silu_f(float v) {
    return v / (1.0f + __expf(-v));
}
__device__ __forceinline__ float2 silu2(float2 v) {
    return make_float2(silu_f(v.x), silu_f(v.y));
}
__device__ __forceinline__ float2 dup2(float w) { return make_float2(w, w); }

// Packed dual-FMA: d = a*b + c lanewise (sm_103a FFMA2, PTX-only)
__device__ __forceinline__ float2 ffma2(float2 a, float2 b, float2 c) {
    float2 d;
    asm("fma.rn.f32x2 %0, %1, %2, %3;"
        : "=l"(*reinterpret_cast<unsigned long long*>(&d))
        : "l"(*reinterpret_cast<unsigned long long*>(&a)),
          "l"(*reinterpret_cast<unsigned long long*>(&b)),
          "l"(*reinterpret_cast<unsigned long long*>(&c)));
    return d;
}

// Load 2 float2 pairs with one LDS.128
__device__ __forceinline__ void ld2pairs(const float2* p, float2& a, float2& b) {
    float4 v = *reinterpret_cast<const float4*>(p);
    a = make_float2(v.x, v.y);
    b = make_float2(v.z, v.w);
}

// ---------------------------------------------------------------------------
__global__ void zero_kernel() {
    int i = blockIdx.x * blockDim.x + threadIdx.x;
    int stride = gridDim.x * blockDim.x;
    for (int idx = i; idx < N_NODES * 384; idx += stride) g_muacc[idx] = 0.0f;
    for (int idx = i; idx < N_NODES * H; idx += stride) g_qacc[idx] = 0.0f;
    for (int idx = i; idx < N_NODES; idx += stride) g_deg[idx] = 0.0f;
}

// ---------------------------------------------------------------------------
// x = silu(q @ Wi1 + bi1) @ Wi2 + bi2        [N,384]
// 8 rows (4 pairs) per block, 128 threads (best-measured config).
// ---------------------------------------------------------------------------
__global__ void __launch_bounds__(128, 8) compute_x_kernel(
    const float* __restrict__ q,
    const float* __restrict__ Wi1, const float* __restrict__ bi1,
    const float* __restrict__ Wi2, const float* __restrict__ bi2)
{
    __shared__ __align__(16) float2 qsT[128][4];
    __shared__ __align__(16) float2 hT[384][4];
    const int t = threadIdx.x;
    const int row0 = blockIdx.x * 8;

    #pragma unroll
    for (int p = 0; p < 4; p++) {
        float lo = q[(row0 + 2 * p) * H + t];
        float hi = q[(row0 + 2 * p + 1) * H + t];
        qsT[t][p] = make_float2(lo, hi);
    }
    __syncthreads();

    float2 a0[4], a1[4], a2[4];
    {
        float2 b0 = dup2(bi1[t]), b1 = dup2(bi1[128 + t]), b2 = dup2(bi1[256 + t]);
        #pragma unroll
        for (int p = 0; p < 4; p++) { a0[p] = b0; a1[p] = b1; a2[p] = b2; }
    }
    #pragma unroll 4
    for (int k = 0; k < 128; k++) {
        float2 w0 = dup2(Wi1[k * 384 + t]);
        float2 w1 = dup2(Wi1[k * 384 + 128 + t]);
        float2 w2 = dup2(Wi1[k * 384 + 256 + t]);
        float2 ap[4];
        ld2pairs(&qsT[k][0], ap[0], ap[1]);
        ld2pairs(&qsT[k][2], ap[2], ap[3]);
        #pragma unroll
        for (int p = 0; p < 4; p++) {
            a0[p] = ffma2(ap[p], w0, a0[p]);
            a1[p] = ffma2(ap[p], w1, a1[p]);
            a2[p] = ffma2(ap[p], w2, a2[p]);
        }
    }
    #pragma unroll
    for (int p = 0; p < 4; p++) {
        hT[t][p]       = silu2(a0[p]);
        hT[128 + t][p] = silu2(a1[p]);
        hT[256 + t][p] = silu2(a2[p]);
    }
    __syncthreads();

    {
        float2 b0 = dup2(bi2[t]), b1 = dup2(bi2[128 + t]), b2 = dup2(bi2[256 + t]);
        #pragma unroll
        for (int p = 0; p < 4; p++) { a0[p] = b0; a1[p] = b1; a2[p] = b2; }
    }
    #pragma unroll 4
    for (int k = 0; k < 384; k++) {
        float2 w0 = dup2(Wi2[k * 384 + t]);
        float2 w1 = dup2(Wi2[k * 384 + 128 + t]);
        float2 w2 = dup2(Wi2[k * 384 + 256 + t]);
        float2 ap[4];
        ld2pairs(&hT[k][0], ap[0], ap[1]);
        ld2pairs(&hT[k][2], ap[2], ap[3]);
        #pragma unroll
        for (int p = 0; p < 4; p++) {
            a0[p] = ffma2(ap[p], w0, a0[p]);
            a1[p] = ffma2(ap[p], w1, a1[p]);
            a2[p] = ffma2(ap[p], w2, a2[p]);
        }
    }
    #pragma unroll
    for (int p = 0; p < 4; p++) {
        size_t base = (size_t)(row0 + 2 * p) * 384;
        g_x[base + t]             = a0[p].x;
        g_x[base + 128 + t]       = a1[p].x;
        g_x[base + 256 + t]       = a2[p].x;
        g_x[base + 384 + t]       = a0[p].y;
        g_x[base + 384 + 128 + t] = a1[p].y;
        g_x[base + 384 + 256 + t] = a2[p].y;
    }
}

// ---------------------------------------------------------------------------
// Fused filter MLP + edge message gather/scatter. 8 edges (4 pairs), 128 thr.
// ---------------------------------------------------------------------------
__global__ void __launch_bounds__(128, 8) edge_fused_kernel(
    const int* __restrict__ edge_index,
    const float* __restrict__ rbf, const float* __restrict__ cutoff,
    const float* __restrict__ unit_vectors, const float* __restrict__ mu,
    const float* __restrict__ Wf1, const float* __restrict__ bf1,
    const float* __restrict__ Wf2, const float* __restrict__ bf2)
{
    __shared__ __align__(16) float2 rbT[20][4];
    __shared__ __align__(16) float2 hT[128][4];
    __shared__ int s_tgt[8], s_src[8];
    __shared__ float s_u[8][3];
    __shared__ float s_cut[8];

    const int t = threadIdx.x;
    const int e0 = blockIdx.x * 8;

    if (t < 8) {
        s_tgt[t] = edge_index[e0 + t];
        s_src[t] = edge_index[N_EDGES + e0 + t];
        s_cut[t] = cutoff[e0 + t];
    }
    if (t < 24) s_u[t / 3][t % 3] = unit_vectors[e0 * 3 + t];
    for (int idx = t; idx < 8 * 20; idx += 128) {   // 160 elements, strided loop
        int e = idx / 20, k = idx % 20;
        reinterpret_cast<float*>(&rbT[k][e >> 1])[e & 1] = rbf[e0 * 20 + idx];
    }
    __syncthreads();

    // layer 1: [E,20] @ [20,128]
    float2 acc1[4];
    {
        float2 b = dup2(bf1[t]);
        #pragma unroll
        for (int p = 0; p < 4; p++) acc1[p] = b;
    }
    #pragma unroll
    for (int k = 0; k < 20; k++) {
        float2 wp = dup2(Wf1[k * 128 + t]);
        float2 ap[4];
        ld2pairs(&rbT[k][0], ap[0], ap[1]);
        ld2pairs(&rbT[k][2], ap[2], ap[3]);
        #pragma unroll
        for (int p = 0; p < 4; p++) acc1[p] = ffma2(ap[p], wp, acc1[p]);
    }
    #pragma unroll
    for (int p = 0; p < 4; p++) hT[t][p] = silu2(acc1[p]);
    __syncthreads();

    // layer 2: [E,128] @ [128,384], filters stay in registers
    float2 f0[4], f1[4], f2[4];
    {
        float2 b0 = dup2(bf2[t]), b1 = dup2(bf2[128 + t]), b2 = dup2(bf2[256 + t]);
        #pragma unroll
        for (int p = 0; p < 4; p++) { f0[p] = b0; f1[p] = b1; f2[p] = b2; }
    }
    #pragma unroll 4
    for (int k = 0; k < 128; k++) {
        float2 w0 = dup2(Wf2[k * 384 + t]);
        float2 w1 = dup2(Wf2[k * 384 + 128 + t]);
        float2 w2 = dup2(Wf2[k * 384 + 256 + t]);
        float2 ap[4];
        ld2pairs(&hT[k][0], ap[0], ap[1]);
        ld2pairs(&hT[k][2], ap[2], ap[3]);
        #pragma unroll
        for (int p = 0; p < 4; p++) {
            f0[p] = ffma2(ap[p], w0, f0[p]);
            f1[p] = ffma2(ap[p], w1, f1[p]);
            f2[p] = ffma2(ap[p], w2, f2[p]);
        }
    }
    #pragma unroll
    for (int p = 0; p < 4; p++) {
        float cx = s_cut[2 * p], cy = s_cut[2 * p + 1];
        f0[p].x *= cx; f0[p].y *= cy;
        f1[p].x *= cx; f1[p].y *= cy;
        f2[p].x *= cx; f2[p].y *= cy;
    }

    // messages: gather x[src], mu[src]; scatter-add
    #pragma unroll
    for (int e = 0; e < 8; e++) {
        const int p = e >> 1;
        const int lane = e & 1;
        float fq = lane ? f0[p].y : f0[p].x;
        float fr = lane ? f1[p].y : f1[p].x;
        float fm = lane ? f2[p].y : f2[p].x;
        int src = s_src[e], tgt = s_tgt[e];
        const float* xs = g_x + (size_t)src * 384;
        const float* ms = mu + (size_t)src * 384;

        atomicAdd(&g_qacc[tgt * H + t], xs[t] * fq);
        float xr = xs[128 + t] * fr;
        float xm = xs[256 + t] * fm;
        atomicAdd(&g_muacc[tgt * 384 + t],       s_u[e][0] * xr + ms[t] * xm);
        atomicAdd(&g_muacc[tgt * 384 + 128 + t], s_u[e][1] * xr + ms[128 + t] * xm);
        atomicAdd(&g_muacc[tgt * 384 + 256 + t], s_u[e][2] * xr + ms[256 + t] * xm);
    }
    if (t < 8) atomicAdd(&g_deg[s_tgt[t]], 1.0f);
}

// ---------------------------------------------------------------------------
// Node update + PaiNN mixing, fused. 8 nodes (4 pairs)/block, 128 threads.
// ---------------------------------------------------------------------------
__global__ void __launch_bounds__(128, 4) node_mixing_kernel(
    const float* __restrict__ q, const float* __restrict__ mu,
    const float* __restrict__ Wv,
    const float* __restrict__ Ws1, const float* __restrict__ bs1,
    const float* __restrict__ Ws2, const float* __restrict__ bs2,
    float* __restrict__ out)
{
    __shared__ __align__(16) float2 munT[384][6];   // [c*128+f][pair]
    __shared__ __align__(16) float2 qnT[128][6];
    __shared__ __align__(16) float2 nrmT[128][6];
    __shared__ __align__(16) float2 hsT[384][6];
    const int t = threadIdx.x;
    const int n0 = blockIdx.x * 8;

    #pragma unroll
    for (int p = 0; p < 4; p++) {
        int na = n0 + 2 * p, nb = na + 1;
        float invA = 1.0f / fmaxf(g_deg[na], 1.0f);
        float invB = 1.0f / fmaxf(g_deg[nb], 1.0f);
        qnT[t][p] = make_float2(q[na * H + t] + g_qacc[na * H + t] * invA,
                                q[nb * H + t] + g_qacc[nb * H + t] * invB);
        #pragma unroll
        for (int c = 0; c < 3; c++) {
            int o = c * 128 + t;
            munT[o][p] = make_float2(
                mu[(size_t)na * 384 + o] + g_muacc[(size_t)na * 384 + o] * invA,
                mu[(size_t)nb * 384 + o] + g_muacc[(size_t)nb * 384 + o] * invB);
        }
    }
    __syncthreads();

    // mu_cat = munew @ Wv; thread t owns mu_v col t and mu_w col t
    float2 v0[4], v1[4], v2[4], w0[4], w1[4], w2[4];
    #pragma unroll
    for (int p = 0; p < 4; p++) {
        v0[p] = v1[p] = v2[p] = make_float2(0.f, 0.f);
        w0[p] = w1[p] = w2[p] = make_float2(0.f, 0.f);
    }
    #pragma unroll 4
    for (int f = 0; f < 128; f++) {
        float2 wv = dup2(Wv[f * 256 + t]);
        float2 ww = dup2(Wv[f * 256 + 128 + t]);
        float2 m0[4], m1[4], m2[4];
        ld2pairs(&munT[f][0],       m0[0], m0[1]);
        ld2pairs(&munT[f][2],       m0[2], m0[3]);
        ld2pairs(&munT[128 + f][0], m1[0], m1[1]);
        ld2pairs(&munT[128 + f][2], m1[2], m1[3]);
        ld2pairs(&munT[256 + f][0], m2[0], m2[1]);
        ld2pairs(&munT[256 + f][2], m2[2], m2[3]);
        #pragma unroll
        for (int p = 0; p < 4; p++) {
            v0[p] = ffma2(m0[p], wv, v0[p]);
            v1[p] = ffma2(m1[p], wv, v1[p]);
            v2[p] = ffma2(m2[p], wv, v2[p]);
            w0[p] = ffma2(m0[p], ww, w0[p]);
            w1[p] = ffma2(m1[p], ww, w1[p]);
            w2[p] = ffma2(m2[p], ww, w2[p]);
        }
    }

    float2 inner[4];
    #pragma unroll
    for (int p = 0; p < 4; p++) {
        nrmT[t][p] = make_float2(
            sqrtf(v0[p].x * v0[p].x + v1[p].x * v1[p].x + v2[p].x * v2[p].x + 1e-8f),
            sqrtf(v0[p].y * v0[p].y + v1[p].y * v1[p].y + v2[p].y * v2[p].y + 1e-8f));
        inner[p] = make_float2(
            v0[p].x * w0[p].x + v1[p].x * w1[p].x + v2[p].x * w2[p].x,
            v0[p].y * w0[p].y + v1[p].y * w1[p].y + v2[p].y * w2[p].y);
    }
    __syncthreads();

    // hidden = silu([qn, nrm] @ Ws1 + bs1)
    float2 a0[4], a1[4], a2[4];
    {
        float2 b0 = dup2(bs1[t]), b1 = dup2(bs1[128 + t]), b2 = dup2(bs1[256 + t]);
        #pragma unroll
        for (int p = 0; p < 4; p++) { a0[p] = b0; a1[p] = b1; a2[p] = b2; }
    }
    #pragma unroll 4
    for (int k = 0; k < 128; k++) {
        float2 x0 = dup2(Ws1[k * 384 + t]);
        float2 x1 = dup2(Ws1[k * 384 + 128 + t]);
        float2 x2 = dup2(Ws1[k * 384 + 256 + t]);
        float2 ap[4];
        ld2pairs(&qnT[k][0], ap[0], ap[1]);
        ld2pairs(&qnT[k][2], ap[2], ap[3]);
        #pragma unroll
        for (int p = 0; p < 4; p++) {
            a0[p] = ffma2(ap[p], x0, a0[p]);
            a1[p] = ffma2(ap[p], x1, a1[p]);
            a2[p] = ffma2(ap[p], x2, a2[p]);
        }
    }
    #pragma unroll 4
    for (int k = 0; k < 128; k++) {
        float2 x0 = dup2(Ws1[(128 + k) * 384 + t]);
        float2 x1 = dup2(Ws1[(128 + k) * 384 + 128 + t]);
        float2 x2 = dup2(Ws1[(128 + k) * 384 + 256 + t]);
        float2 ap[4];
        ld2pairs(&nrmT[k][0], ap[0], ap[1]);
        ld2pairs(&nrmT[k][2], ap[2], ap[3]);
        #pragma unroll
        for (int p = 0; p < 4; p++) {
            a0[p] = ffma2(ap[p], x0, a0[p]);
            a1[p] = ffma2(ap[p], x1, a1[p]);
            a2[p] = ffma2(ap[p], x2, a2[p]);
        }
    }
    #pragma unroll
    for (int p = 0; p < 4; p++) {
        hsT[t][p]       = silu2(a0[p]);
        hsT[128 + t][p] = silu2(a1[p]);
        hsT[256 + t][p] = silu2(a2[p]);
    }
    __syncthreads();

    // delta = hs @ Ws2 + bs2; a0=dq, a1=dmu_scale, a2=dqmu
    {
        float2 b0 = dup2(bs2[t]), b1 = dup2(bs2[128 + t]), b2 = dup2(bs2[256 + t]);
        #pragma unroll
        for (int p = 0; p < 4; p++) { a0[p] = b0; a1[p] = b1; a2[p] = b2; }
    }
    #pragma unroll 4
    for (int k = 0; k < 384; k++) {
        float2 x0 = dup2(Ws2[k * 384 + t]);
        float2 x1 = dup2(Ws2[k * 384 + 128 + t]);
        float2 x2 = dup2(Ws2[k * 384 + 256 + t]);
        float2 ap[4];
        ld2pairs(&hsT[k][0], ap[0], ap[1]);
        ld2pairs(&hsT[k][2], ap[2], ap[3]);
        #pragma unroll
        for (int p = 0; p < 4; p++) {
            a0[p] = ffma2(ap[p], x0, a0[p]);
            a1[p] = ffma2(ap[p], x1, a1[p]);
            a2[p] = ffma2(ap[p], x2, a2[p]);
        }
    }

    #pragma unroll
    for (int p = 0; p < 4; p++) {
        int na = n0 + 2 * p, nb = na + 1;
        float2 qv = qnT[t][p];
        out[na * H + t] = qv.x + a0[p].x + a2[p].x * inner[p].x;
        out[nb * H + t] = qv.y + a0[p].y + a2[p].y * inner[p].y;
        float* moutA = out + (size_t)N_NODES * H + (size_t)na * 384;
        float* moutB = moutA + 384;
        float2 mA0 = munT[t][p], mA1 = munT[128 + t][p], mA2 = munT[256 + t][p];
        moutA[t]       = mA0.x + w0[p].x * a1[p].x;
        moutA[128 + t] = mA1.x + w1[p].x * a1[p].x;
        moutA[256 + t] = mA2.x + w2[p].x * a1[p].x;
        moutB[t]       = mA0.y + w0[p].y * a1[p].y;
        moutB[128 + t] = mA1.y + w1[p].y * a1[p].y;
        moutB[256 + t] = mA2.y + w2[p].y * a1[p].y;
    }
}

// ---------------------------------------------------------------------------
extern "C" void kernel_launch(void* const* d_in, const int* in_sizes, int n_in,
                              void* d_out, int out_size) {
    const float* q            = (const float*)d_in[0];
    const float* mu           = (const float*)d_in[1];
    const int*   edge_index   = (const int*)d_in[2];
    const float* rbf          = (const float*)d_in[3];
    const float* unit_vectors = (const float*)d_in[4];
    const float* cutoff       = (const float*)d_in[5];
    const float* Wi1 = (const float*)d_in[6];
    const float* bi1 = (const float*)d_in[7];
    const float* Wi2 = (const float*)d_in[8];
    const float* bi2 = (const float*)d_in[9];
    const float* Wf1 = (const float*)d_in[10];
    const float* bf1 = (const float*)d_in[11];
    const float* Wf2 = (const float*)d_in[12];
    const float* bf2 = (const float*)d_in[13];
    const float* Wv  = (const float*)d_in[14];
    const float* Ws1 = (const float*)d_in[15];
    const float* bs1 = (const float*)d_in[16];
    const float* Ws2 = (const float*)d_in[17];
    const float* bs2 = (const float*)d_in[18];
    float* out = (float*)d_out;

    zero_kernel<<<1024, 256>>>();
    compute_x_kernel<<<N_NODES / 8, 128>>>(q, Wi1, bi1, Wi2, bi2);
    edge_fused_kernel<<<N_EDGES / 8, 128>>>(edge_index, rbf, cutoff,
                                            unit_vectors, mu,
                                            Wf1, bf1, Wf2, bf2);
    node_mixing_kernel<<<N_NODES / 8, 128>>>(q, mu, Wv, Ws1, bs1, Ws2, bs2, out);
}

// round 17
// speedup vs baseline: 1.0020x; 1.0020x over previous
#include <cuda_runtime.h>

#define N_NODES 32768
#define N_EDGES 262144
#define H 128

// Scratch (device globals — no allocation allowed). 16B-aligned for STG.128.
__device__ __align__(16) float g_x[N_NODES * 384];      // interaction MLP output
__device__ __align__(16) float g_qacc[N_NODES * H];     // scalar message accumulator
__device__ __align__(16) float g_muacc[N_NODES * 384];  // vector message accumulator
__device__ __align__(16) float g_deg[N_NODES];          // in-degree

__device__ __forceinline__ float silu_f(float v) {
    return v / (1.0f + __expf(-v));
}
__device__ __forceinline__ float2 silu2(float2 v) {
    return make_float2(silu_f(v.x), silu_f(v.y));
}
__device__ __forceinline__ float2 dup2(float w) { return make_float2(w, w); }

// Packed dual-FMA: d = a*b + c lanewise (sm_103a FFMA2, PTX-only)
__device__ __forceinline__ float2 ffma2(float2 a, float2 b, float2 c) {
    float2 d;
    asm("fma.rn.f32x2 %0, %1, %2, %3;"
        : "=l"(*reinterpret_cast<unsigned long long*>(&d))
        : "l"(*reinterpret_cast<unsigned long long*>(&a)),
          "l"(*reinterpret_cast<unsigned long long*>(&b)),
          "l"(*reinterpret_cast<unsigned long long*>(&c)));
    return d;
}

// Load 2 float2 pairs with one LDS.128
__device__ __forceinline__ void ld2pairs(const float2* p, float2& a, float2& b) {
    float4 v = *reinterpret_cast<const float4*>(p);
    a = make_float2(v.x, v.y);
    b = make_float2(v.z, v.w);
}

// ---------------------------------------------------------------------------
// Zero accumulators with vector stores (STG.128). All counts divisible by 4.
// ---------------------------------------------------------------------------
__global__ void zero_kernel() {
    const float4 z = make_float4(0.f, 0.f, 0.f, 0.f);
    int i = blockIdx.x * blockDim.x + threadIdx.x;
    int stride = gridDim.x * blockDim.x;
    float4* mu4 = reinterpret_cast<float4*>(g_muacc);
    float4* q4  = reinterpret_cast<float4*>(g_qacc);
    float4* d4  = reinterpret_cast<float4*>(g_deg);
    for (int idx = i; idx < N_NODES * 384 / 4; idx += stride) mu4[idx] = z;
    for (int idx = i; idx < N_NODES * H / 4; idx += stride) q4[idx] = z;
    for (int idx = i; idx < N_NODES / 4; idx += stride) d4[idx] = z;
}

// ---------------------------------------------------------------------------
// x = silu(q @ Wi1 + bi1) @ Wi2 + bi2        [N,384]
// 8 rows (4 pairs) per block, 128 threads (best-measured config).
// ---------------------------------------------------------------------------
__global__ void __launch_bounds__(128, 8) compute_x_kernel(
    const float* __restrict__ q,
    const float* __restrict__ Wi1, const float* __restrict__ bi1,
    const float* __restrict__ Wi2, const float* __restrict__ bi2)
{
    __shared__ __align__(16) float2 qsT[128][4];
    __shared__ __align__(16) float2 hT[384][4];
    const int t = threadIdx.x;
    const int row0 = blockIdx.x * 8;

    #pragma unroll
    for (int p = 0; p < 4; p++) {
        float lo = q[(row0 + 2 * p) * H + t];
        float hi = q[(row0 + 2 * p + 1) * H + t];
        qsT[t][p] = make_float2(lo, hi);
    }
    __syncthreads();

    float2 a0[4], a1[4], a2[4];
    {
        float2 b0 = dup2(bi1[t]), b1 = dup2(bi1[128 + t]), b2 = dup2(bi1[256 + t]);
        #pragma unroll
        for (int p = 0; p < 4; p++) { a0[p] = b0; a1[p] = b1; a2[p] = b2; }
    }
    #pragma unroll 4
    for (int k = 0; k < 128; k++) {
        float2 w0 = dup2(Wi1[k * 384 + t]);
        float2 w1 = dup2(Wi1[k * 384 + 128 + t]);
        float2 w2 = dup2(Wi1[k * 384 + 256 + t]);
        float2 ap[4];
        ld2pairs(&qsT[k][0], ap[0], ap[1]);
        ld2pairs(&qsT[k][2], ap[2], ap[3]);
        #pragma unroll
        for (int p = 0; p < 4; p++) {
            a0[p] = ffma2(ap[p], w0, a0[p]);
            a1[p] = ffma2(ap[p], w1, a1[p]);
            a2[p] = ffma2(ap[p], w2, a2[p]);
        }
    }
    #pragma unroll
    for (int p = 0; p < 4; p++) {
        hT[t][p]       = silu2(a0[p]);
        hT[128 + t][p] = silu2(a1[p]);
        hT[256 + t][p] = silu2(a2[p]);
    }
    __syncthreads();

    {
        float2 b0 = dup2(bi2[t]), b1 = dup2(bi2[128 + t]), b2 = dup2(bi2[256 + t]);
        #pragma unroll
        for (int p = 0; p < 4; p++) { a0[p] = b0; a1[p] = b1; a2[p] = b2; }
    }
    #pragma unroll 4
    for (int k = 0; k < 384; k++) {
        float2 w0 = dup2(Wi2[k * 384 + t]);
        float2 w1 = dup2(Wi2[k * 384 + 128 + t]);
        float2 w2 = dup2(Wi2[k * 384 + 256 + t]);
        float2 ap[4];
        ld2pairs(&hT[k][0], ap[0], ap[1]);
        ld2pairs(&hT[k][2], ap[2], ap[3]);
        #pragma unroll
        for (int p = 0; p < 4; p++) {
            a0[p] = ffma2(ap[p], w0, a0[p]);
            a1[p] = ffma2(ap[p], w1, a1[p]);
            a2[p] = ffma2(ap[p], w2, a2[p]);
        }
    }
    #pragma unroll
    for (int p = 0; p < 4; p++) {
        size_t base = (size_t)(row0 + 2 * p) * 384;
        g_x[base + t]             = a0[p].x;
        g_x[base + 128 + t]       = a1[p].x;
        g_x[base + 256 + t]       = a2[p].x;
        g_x[base + 384 + t]       = a0[p].y;
        g_x[base + 384 + 128 + t] = a1[p].y;
        g_x[base + 384 + 256 + t] = a2[p].y;
    }
}

// ---------------------------------------------------------------------------
// Fused filter MLP + edge message gather/scatter. 8 edges (4 pairs), 128 thr.
// ---------------------------------------------------------------------------
__global__ void __launch_bounds__(128, 8) edge_fused_kernel(
    const int* __restrict__ edge_index,
    const float* __restrict__ rbf, const float* __restrict__ cutoff,
    const float* __restrict__ unit_vectors, const float* __restrict__ mu,
    const float* __restrict__ Wf1, const float* __restrict__ bf1,
    const float* __restrict__ Wf2, const float* __restrict__ bf2)
{
    __shared__ __align__(16) float2 rbT[20][4];
    __shared__ __align__(16) float2 hT[128][4];
    __shared__ int s_tgt[8], s_src[8];
    __shared__ float s_u[8][3];
    __shared__ float s_cut[8];

    const int t = threadIdx.x;
    const int e0 = blockIdx.x * 8;

    if (t < 8) {
        s_tgt[t] = edge_index[e0 + t];
        s_src[t] = edge_index[N_EDGES + e0 + t];
        s_cut[t] = cutoff[e0 + t];
    }
    if (t < 24) s_u[t / 3][t % 3] = unit_vectors[e0 * 3 + t];
    for (int idx = t; idx < 8 * 20; idx += 128) {   // 160 elements, strided loop
        int e = idx / 20, k = idx % 20;
        reinterpret_cast<float*>(&rbT[k][e >> 1])[e & 1] = rbf[e0 * 20 + idx];
    }
    __syncthreads();

    // layer 1: [E,20] @ [20,128]
    float2 acc1[4];
    {
        float2 b = dup2(bf1[t]);
        #pragma unroll
        for (int p = 0; p < 4; p++) acc1[p] = b;
    }
    #pragma unroll
    for (int k = 0; k < 20; k++) {
        float2 wp = dup2(Wf1[k * 128 + t]);
        float2 ap[4];
        ld2pairs(&rbT[k][0], ap[0], ap[1]);
        ld2pairs(&rbT[k][2], ap[2], ap[3]);
        #pragma unroll
        for (int p = 0; p < 4; p++) acc1[p] = ffma2(ap[p], wp, acc1[p]);
    }
    #pragma unroll
    for (int p = 0; p < 4; p++) hT[t][p] = silu2(acc1[p]);
    __syncthreads();

    // layer 2: [E,128] @ [128,384], filters stay in registers
    float2 f0[4], f1[4], f2[4];
    {
        float2 b0 = dup2(bf2[t]), b1 = dup2(bf2[128 + t]), b2 = dup2(bf2[256 + t]);
        #pragma unroll
        for (int p = 0; p < 4; p++) { f0[p] = b0; f1[p] = b1; f2[p] = b2; }
    }
    #pragma unroll 4
    for (int k = 0; k < 128; k++) {
        float2 w0 = dup2(Wf2[k * 384 + t]);
        float2 w1 = dup2(Wf2[k * 384 + 128 + t]);
        float2 w2 = dup2(Wf2[k * 384 + 256 + t]);
        float2 ap[4];
        ld2pairs(&hT[k][0], ap[0], ap[1]);
        ld2pairs(&hT[k][2], ap[2], ap[3]);
        #pragma unroll
        for (int p = 0; p < 4; p++) {
            f0[p] = ffma2(ap[p], w0, f0[p]);
            f1[p] = ffma2(ap[p], w1, f1[p]);
            f2[p] = ffma2(ap[p], w2, f2[p]);
        }
    }
    #pragma unroll
    for (int p = 0; p < 4; p++) {
        float cx = s_cut[2 * p], cy = s_cut[2 * p + 1];
        f0[p].x *= cx; f0[p].y *= cy;
        f1[p].x *= cx; f1[p].y *= cy;
        f2[p].x *= cx; f2[p].y *= cy;
    }

    // messages: gather x[src], mu[src]; scatter-add
    #pragma unroll
    for (int e = 0; e < 8; e++) {
        const int p = e >> 1;
        const int lane = e & 1;
        float fq = lane ? f0[p].y : f0[p].x;
        float fr = lane ? f1[p].y : f1[p].x;
        float fm = lane ? f2[p].y : f2[p].x;
        int src = s_src[e], tgt = s_tgt[e];
        const float* xs = g_x + (size_t)src * 384;
        const float* ms = mu + (size_t)src * 384;

        atomicAdd(&g_qacc[tgt * H + t], xs[t] * fq);
        float xr = xs[128 + t] * fr;
        float xm = xs[256 + t] * fm;
        atomicAdd(&g_muacc[tgt * 384 + t],       s_u[e][0] * xr + ms[t] * xm);
        atomicAdd(&g_muacc[tgt * 384 + 128 + t], s_u[e][1] * xr + ms[128 + t] * xm);
        atomicAdd(&g_muacc[tgt * 384 + 256 + t], s_u[e][2] * xr + ms[256 + t] * xm);
    }
    if (t < 8) atomicAdd(&g_deg[s_tgt[t]], 1.0f);
}

// ---------------------------------------------------------------------------
// Node update + PaiNN mixing, fused. 8 nodes (4 pairs)/block, 128 threads.
// ---------------------------------------------------------------------------
__global__ void __launch_bounds__(128, 4) node_mixing_kernel(
    const float* __restrict__ q, const float* __restrict__ mu,
    const float* __restrict__ Wv,
    const float* __restrict__ Ws1, const float* __restrict__ bs1,
    const float* __restrict__ Ws2, const float* __restrict__ bs2,
    float* __restrict__ out)
{
    __shared__ __align__(16) float2 munT[384][6];   // [c*128+f][pair]
    __shared__ __align__(16) float2 qnT[128][6];
    __shared__ __align__(16) float2 nrmT[128][6];
    __shared__ __align__(16) float2 hsT[384][6];
    const int t = threadIdx.x;
    const int n0 = blockIdx.x * 8;

    #pragma unroll
    for (int p = 0; p < 4; p++) {
        int na = n0 + 2 * p, nb = na + 1;
        float invA = 1.0f / fmaxf(g_deg[na], 1.0f);
        float invB = 1.0f / fmaxf(g_deg[nb], 1.0f);
        qnT[t][p] = make_float2(q[na * H + t] + g_qacc[na * H + t] * invA,
                                q[nb * H + t] + g_qacc[nb * H + t] * invB);
        #pragma unroll
        for (int c = 0; c < 3; c++) {
            int o = c * 128 + t;
            munT[o][p] = make_float2(
                mu[(size_t)na * 384 + o] + g_muacc[(size_t)na * 384 + o] * invA,
                mu[(size_t)nb * 384 + o] + g_muacc[(size_t)nb * 384 + o] * invB);
        }
    }
    __syncthreads();

    // mu_cat = munew @ Wv; thread t owns mu_v col t and mu_w col t
    float2 v0[4], v1[4], v2[4], w0[4], w1[4], w2[4];
    #pragma unroll
    for (int p = 0; p < 4; p++) {
        v0[p] = v1[p] = v2[p] = make_float2(0.f, 0.f);
        w0[p] = w1[p] = w2[p] = make_float2(0.f, 0.f);
    }
    #pragma unroll 4
    for (int f = 0; f < 128; f++) {
        float2 wv = dup2(Wv[f * 256 + t]);
        float2 ww = dup2(Wv[f * 256 + 128 + t]);
        float2 m0[4], m1[4], m2[4];
        ld2pairs(&munT[f][0],       m0[0], m0[1]);
        ld2pairs(&munT[f][2],       m0[2], m0[3]);
        ld2pairs(&munT[128 + f][0], m1[0], m1[1]);
        ld2pairs(&munT[128 + f][2], m1[2], m1[3]);
        ld2pairs(&munT[256 + f][0], m2[0], m2[1]);
        ld2pairs(&munT[256 + f][2], m2[2], m2[3]);
        #pragma unroll
        for (int p = 0; p < 4; p++) {
            v0[p] = ffma2(m0[p], wv, v0[p]);
            v1[p] = ffma2(m1[p], wv, v1[p]);
            v2[p] = ffma2(m2[p], wv, v2[p]);
            w0[p] = ffma2(m0[p], ww, w0[p]);
            w1[p] = ffma2(m1[p], ww, w1[p]);
            w2[p] = ffma2(m2[p], ww, w2[p]);
        }
    }

    float2 inner[4];
    #pragma unroll
    for (int p = 0; p < 4; p++) {
        nrmT[t][p] = make_float2(
            sqrtf(v0[p].x * v0[p].x + v1[p].x * v1[p].x + v2[p].x * v2[p].x + 1e-8f),
            sqrtf(v0[p].y * v0[p].y + v1[p].y * v1[p].y + v2[p].y * v2[p].y + 1e-8f));
        inner[p] = make_float2(
            v0[p].x * w0[p].x + v1[p].x * w1[p].x + v2[p].x * w2[p].x,
            v0[p].y * w0[p].y + v1[p].y * w1[p].y + v2[p].y * w2[p].y);
    }
    __syncthreads();

    // hidden = silu([qn, nrm] @ Ws1 + bs1)
    float2 a0[4], a1[4], a2[4];
    {
        float2 b0 = dup2(bs1[t]), b1 = dup2(bs1[128 + t]), b2 = dup2(bs1[256 + t]);
        #pragma unroll
        for (int p = 0; p < 4; p++) { a0[p] = b0; a1[p] = b1; a2[p] = b2; }
    }
    #pragma unroll 4
    for (int k = 0; k < 128; k++) {
        float2 x0 = dup2(Ws1[k * 384 + t]);
        float2 x1 = dup2(Ws1[k * 384 + 128 + t]);
        float2 x2 = dup2(Ws1[k * 384 + 256 + t]);
        float2 ap[4];
        ld2pairs(&qnT[k][0], ap[0], ap[1]);
        ld2pairs(&qnT[k][2], ap[2], ap[3]);
        #pragma unroll
        for (int p = 0; p < 4; p++) {
            a0[p] = ffma2(ap[p], x0, a0[p]);
            a1[p] = ffma2(ap[p], x1, a1[p]);
            a2[p] = ffma2(ap[p], x2, a2[p]);
        }
    }
    #pragma unroll 4
    for (int k = 0; k < 128; k++) {
        float2 x0 = dup2(Ws1[(128 + k) * 384 + t]);
        float2 x1 = dup2(Ws1[(128 + k) * 384 + 128 + t]);
        float2 x2 = dup2(Ws1[(128 + k) * 384 + 256 + t]);
        float2 ap[4];
        ld2pairs(&nrmT[k][0], ap[0], ap[1]);
        ld2pairs(&nrmT[k][2], ap[2], ap[3]);
        #pragma unroll
        for (int p = 0; p < 4; p++) {
            a0[p] = ffma2(ap[p], x0, a0[p]);
            a1[p] = ffma2(ap[p], x1, a1[p]);
            a2[p] = ffma2(ap[p], x2, a2[p]);
        }
    }
    #pragma unroll
    for (int p = 0; p < 4; p++) {
        hsT[t][p]       = silu2(a0[p]);
        hsT[128 + t][p] = silu2(a1[p]);
        hsT[256 + t][p] = silu2(a2[p]);
    }
    __syncthreads();

    // delta = hs @ Ws2 + bs2; a0=dq, a1=dmu_scale, a2=dqmu
    {
        float2 b0 = dup2(bs2[t]), b1 = dup2(bs2[128 + t]), b2 = dup2(bs2[256 + t]);
        #pragma unroll
        for (int p = 0; p < 4; p++) { a0[p] = b0; a1[p] = b1; a2[p] = b2; }
    }
    #pragma unroll 4
    for (int k = 0; k < 384; k++) {
        float2 x0 = dup2(Ws2[k * 384 + t]);
        float2 x1 = dup2(Ws2[k * 384 + 128 + t]);
        float2 x2 = dup2(Ws2[k * 384 + 256 + t]);
        float2 ap[4];
        ld2pairs(&hsT[k][0], ap[0], ap[1]);
        ld2pairs(&hsT[k][2], ap[2], ap[3]);
        #pragma unroll
        for (int p = 0; p < 4; p++) {
            a0[p] = ffma2(ap[p], x0, a0[p]);
            a1[p] = ffma2(ap[p], x1, a1[p]);
            a2[p] = ffma2(ap[p], x2, a2[p]);
        }
    }

    #pragma unroll
    for (int p = 0; p < 4; p++) {
        int na = n0 + 2 * p, nb = na + 1;
        float2 qv = qnT[t][p];
        out[na * H + t] = qv.x + a0[p].x + a2[p].x * inner[p].x;
        out[nb * H + t] = qv.y + a0[p].y + a2[p].y * inner[p].y;
        float* moutA = out + (size_t)N_NODES * H + (size_t)na * 384;
        float* moutB = moutA + 384;
        float2 mA0 = munT[t][p], mA1 = munT[128 + t][p], mA2 = munT[256 + t][p];
        moutA[t]       = mA0.x + w0[p].x * a1[p].x;
        moutA[128 + t] = mA1.x + w1[p].x * a1[p].x;
        moutA[256 + t] = mA2.x + w2[p].x * a1[p].x;
        moutB[t]       = mA0.y + w0[p].y * a1[p].y;
        moutB[128 + t] = mA1.y + w1[p].y * a1[p].y;
        moutB[256 + t] = mA2.y + w2[p].y * a1[p].y;
    }
}

// ---------------------------------------------------------------------------
extern "C" void kernel_launch(void* const* d_in, const int* in_sizes, int n_in,
                              void* d_out, int out_size) {
    const float* q            = (const float*)d_in[0];
    const float* mu           = (const float*)d_in[1];
    const int*   edge_index   = (const int*)d_in[2];
    const float* rbf          = (const float*)d_in[3];
    const float* unit_vectors = (const float*)d_in[4];
    const float* cutoff       = (const float*)d_in[5];
    const float* Wi1 = (const float*)d_in[6];
    const float* bi1 = (const float*)d_in[7];
    const float* Wi2 = (const float*)d_in[8];
    const float* bi2 = (const float*)d_in[9];
    const float* Wf1 = (const float*)d_in[10];
    const float* bf1 = (const float*)d_in[11];
    const float* Wf2 = (const float*)d_in[12];
    const float* bf2 = (const float*)d_in[13];
    const float* Wv  = (const float*)d_in[14];
    const float* Ws1 = (const float*)d_in[15];
    const float* bs1 = (const float*)d_in[16];
    const float* Ws2 = (const float*)d_in[17];
    const float* bs2 = (const float*)d_in[18];
    float* out = (float*)d_out;

    zero_kernel<<<1024, 256>>>();
    compute_x_kernel<<<N_NODES / 8, 128>>>(q, Wi1, bi1, Wi2, bi2);
    edge_fused_kernel<<<N_EDGES / 8, 128>>>(edge_index, rbf, cutoff,
                                            unit_vectors, mu,
                                            Wf1, bf1, Wf2, bf2);
    node_mixing_kernel<<<N_NODES / 8, 128>>>(q, mu, Wv, Ws1, bs1, Ws2, bs2, out);
}